// round 15
// baseline (speedup 1.0000x reference)
#include <cuda_runtime.h>
#include <cuda_fp16.h>
#include <stdint.h>
#include <math.h>

#define B_    64
#define I_    48
#define O_    48
#define F_    256
#define H_    256
#define FIVEH 1280
#define NCTA  444               // 3 CTAs per SM, 148 SMs

// smem per stage: B tile 160x64 fp16 (rows stride 144B) + A 64x64 fp16
#define BBYTES 23040                 // 160*144
#define APASS  9216                  // 64*144
#define STAGE  (BBYTES + APASS)      // 32256
#define NSTAGE 2
#define SMEM_TOTAL (NSTAGE*STAGE)    // 64512 (epilogue reuse: 64*160*4 = 40960)

#define CELLS (I_ * O_)              // 2304

// ---------------- scratch (device globals) ----------------------------------
__device__ float g_PX[I_ * B_ * FIVEH];          // [i][b][g*256+h]
__device__ float g_PY[O_ * B_ * FIVEH];
__device__ __half g_Wh[FIVEH * 512];             // W' fp16, [n'][k], n'=h*5+g
__device__ __half g_S16[(size_t)CELLS * B_ * H_];// s per cell (i*O+j), fp16
__device__ float  g_C[(size_t)CELLS * B_ * H_];  // c per cell, fp32
__device__ unsigned g_cnt[CELLS];                // per-cell completion counters

// ---------------- fast transcendentals (MUFU path) ---------------------------
__device__ __forceinline__ float sigf(float x) {
    return __fdividef(1.f, 1.f + __expf(-x));
}
__device__ __forceinline__ float tanhf_fast(float x) {
    float xc = fminf(fmaxf(x, -15.f), 15.f);
    float e = __expf(2.f * xc);
    return __fdividef(e - 1.f, e + 1.f);
}

__device__ __forceinline__ uint32_t smem_u32(const void* p) {
    uint32_t a;
    asm("{ .reg .u64 t; cvta.to.shared.u64 t, %1; cvt.u32.u64 %0, t; }" : "=r"(a) : "l"(p));
    return a;
}
__device__ __forceinline__ void cp16(uint32_t dst, const void* src) {
    asm volatile("cp.async.cg.shared.global [%0], [%1], 16;"
                 :: "r"(dst), "l"(src) : "memory");
}
#define CP_COMMIT() asm volatile("cp.async.commit_group;" ::: "memory")
#define CP_WAIT(n)  asm volatile("cp.async.wait_group %0;" :: "n"(n) : "memory")

__device__ __forceinline__ void ldmA(uint32_t* a, uint32_t addr) {
    asm volatile("ldmatrix.sync.aligned.m8n8.x4.shared.b16 {%0,%1,%2,%3}, [%4];"
                 : "=r"(a[0]), "=r"(a[1]), "=r"(a[2]), "=r"(a[3]) : "r"(addr));
}
__device__ __forceinline__ void ldmB(uint32_t* b, uint32_t addr) {
    asm volatile("ldmatrix.sync.aligned.m8n8.x2.shared.b16 {%0,%1}, [%2];"
                 : "=r"(b[0]), "=r"(b[1]) : "r"(addr));
}
__device__ __forceinline__ void mma16816(float* c, const uint32_t* a, const uint32_t* b) {
    asm volatile("mma.sync.aligned.m16n8k16.row.col.f32.f16.f16.f32 "
                 "{%0,%1,%2,%3}, {%4,%5,%6,%7}, {%8,%9}, {%0,%1,%2,%3};"
                 : "+f"(c[0]), "+f"(c[1]), "+f"(c[2]), "+f"(c[3])
                 : "r"(a[0]), "r"(a[1]), "r"(a[2]), "r"(a[3]), "r"(b[0]), "r"(b[1]));
}

// ---------------- dataflow flag helpers --------------------------------------
__device__ __forceinline__ void wait_cell(const unsigned* p) {
    unsigned v;
    do {
        asm volatile("ld.acquire.gpu.global.u32 %0, [%1];" : "=r"(v) : "l"(p));
    } while (v < 8u);
}
__device__ __forceinline__ void signal_cell(unsigned* p) {
    asm volatile("red.release.gpu.global.add.u32 [%0], 1;" :: "l"(p) : "memory");
}

// ---------------------------------------------------------------------------
// Setup kernels
// ---------------------------------------------------------------------------
__global__ void zero_cnt_kernel() {
    int idx = blockIdx.x * 256 + threadIdx.x;
    if (idx < CELLS) g_cnt[idx] = 0u;
}

__global__ __launch_bounds__(256) void split_ws_kernel(const float* __restrict__ Ws) {
    int idx = blockIdx.x * 256 + threadIdx.x;
    if (idx >= FIVEH * 512) return;
    int np = idx >> 9, k = idx & 511;
    int h = np / 5, g = np % 5;
    g_Wh[idx] = __float2half(Ws[k * FIVEH + g * H_ + h]);
}

__global__ __launch_bounds__(256) void precompute_kernel(
    const float* __restrict__ x, const float* __restrict__ y,
    const float* __restrict__ Wx)
{
    const int cell = blockIdx.x, n0 = blockIdx.y * 128, which = blockIdx.z;
    const float* A = which ? y : x;
    const int koff = which ? F_ : 0;
    float* P = which ? g_PY : g_PX;

    __shared__ float As[16][68];
    __shared__ float Bs[16][128];
    const int t = threadIdx.x;
    const int tx = t & 15, ty = t >> 4;
    const int lm = t >> 2, lk = (t & 3) * 4;

    float acc[4][8];
#pragma unroll
    for (int r = 0; r < 4; r++)
#pragma unroll
        for (int q = 0; q < 8; q++) acc[r][q] = 0.f;

    for (int k0 = 0; k0 < F_; k0 += 16) {
        float4 av = *(const float4*)&A[(lm * I_ + cell) * F_ + k0 + lk];
        As[lk + 0][lm] = av.x; As[lk + 1][lm] = av.y;
        As[lk + 2][lm] = av.z; As[lk + 3][lm] = av.w;
#pragma unroll
        for (int s = 0; s < 2; s++) {
            int idx = t + 256 * s;
            int kl = idx >> 5, c4 = idx & 31;
            *(float4*)&Bs[kl][c4 * 4] =
                *(const float4*)&Wx[(koff + k0 + kl) * FIVEH + n0 + c4 * 4];
        }
        __syncthreads();
#pragma unroll
        for (int k = 0; k < 16; k++) {
            float4 a4 = *(const float4*)&As[k][ty * 4];
            float4 b0 = *(const float4*)&Bs[k][tx * 8];
            float4 b1 = *(const float4*)&Bs[k][tx * 8 + 4];
            float a[4] = {a4.x, a4.y, a4.z, a4.w};
            float bb[8] = {b0.x, b0.y, b0.z, b0.w, b1.x, b1.y, b1.z, b1.w};
#pragma unroll
            for (int r = 0; r < 4; r++)
#pragma unroll
                for (int q = 0; q < 8; q++) acc[r][q] += a[r] * bb[q];
        }
        __syncthreads();
    }
#pragma unroll
    for (int r = 0; r < 4; r++) {
        int m = ty * 4 + r;
        float* dst = &P[(cell * B_ + m) * FIVEH + n0 + tx * 8];
        *(float4*)dst       = make_float4(acc[r][0], acc[r][1], acc[r][2], acc[r][3]);
        *(float4*)(dst + 4) = make_float4(acc[r][4], acc[r][5], acc[r][6], acc[r][7]);
    }
}

// ---------------------------------------------------------------------------
// Fused tile: cell (i,j) x 32-h slice; waits on neighbor cells' flags.
// K = 512 single-term fp16 (s@W), hor/ver 256-k halves skipped at edges.
// 2-stage cp.async pipeline; first B chunk prefetched BEFORE the flag wait;
// hor/ver flags polled by two threads in parallel.
// ---------------------------------------------------------------------------
__device__ __forceinline__ void fused_tile(
    char* smem, uint32_t sb,
    const float* __restrict__ bias, float* __restrict__ out,
    int i, int j, int htile)
{
    const int t = threadIdx.x, wid = t >> 5, lane = t & 31;
    const bool hh = (i > 0), vv = (j > 0);
    const int n_base = htile * 160;
    const int cell  = i * O_ + j;
    const int cellH = cell - O_;      // (i-1, j)
    const int cellV = cell - 1;       // (i, j-1)

    const __half* __restrict__ SH = g_S16 + (size_t)cellH * (B_ * H_);
    const __half* __restrict__ SV = g_S16 + (size_t)cellV * (B_ * H_);
    const float* __restrict__ CH = g_C + (size_t)cellH * (B_ * H_);
    const float* __restrict__ CV = g_C + (size_t)cellV * (B_ * H_);

    // active 64-k chunks (sc 0..3 hor, 4..7 ver)
    int scs[8], nsc = 0;
    if (hh) { scs[0] = 0; scs[1] = 1; scs[2] = 2; scs[3] = 3; nsc = 4; }
    if (vv) { scs[nsc] = 4; scs[nsc + 1] = 5; scs[nsc + 2] = 6; scs[nsc + 3] = 7; nsc += 4; }

    auto load_B = [&](int sc, int buf) {
        const uint32_t base = sb + buf * STAGE;
        const int kb = sc * 64;
#pragma unroll
        for (int p = 0; p < 5; p++) {
            int idx = t + 256 * p;
            int r = idx >> 3, seg = idx & 7;
            cp16(base + r * 144 + seg * 16,
                 g_Wh + (size_t)(n_base + r) * 512 + kb + seg * 8);
        }
    };
    auto load_A = [&](int sc, int buf) {
        const uint32_t base = sb + buf * STAGE;
        const __half* S = (sc < 4) ? SH : SV;
        const int kc = (sc & 3) * 64;
#pragma unroll
        for (int p = 0; p < 2; p++) {
            int idx = t + 256 * p;
            int b = idx >> 3, seg = idx & 7;
            cp16(base + BBYTES + b * 144 + seg * 16,
                 S + (size_t)b * H_ + kc + seg * 8);
        }
    };

    // ---- prefetch first B chunk (no deps), then PARALLEL dependency waits ----
    if (nsc) load_B(scs[0], 0);          // issued, not yet committed
    if (t == 0  && hh) wait_cell(&g_cnt[cellH]);
    if (t == 32 && vv) wait_cell(&g_cnt[cellV]);
    __syncthreads();

    // warp tiling: 2m x 4n; warp tile m32 x n40
    const int wm = wid & 1, wn = wid >> 1;
    const int m0 = wm * 32, n0 = wn * 40;
    const uint32_t arow = (uint32_t)(BBYTES + (m0 + ((lane >> 3) & 1) * 8 + (lane & 7)) * 144
                                     + (lane >> 4) * 16);
    const uint32_t brow = (uint32_t)((n0 + (lane & 7)) * 144 + ((lane >> 3) & 1) * 16);

    float acc[2][5][4];
#pragma unroll
    for (int f = 0; f < 2; f++)
#pragma unroll
        for (int e = 0; e < 5; e++)
#pragma unroll
            for (int q = 0; q < 4; q++) acc[f][e][q] = 0.f;

    if (nsc) {
        load_A(scs[0], 0);
        CP_COMMIT();                     // group 0: B0 + A0

        for (int idx = 0; idx < nsc; idx++) {
            if (idx + 1 < nsc) {
                load_B(scs[idx + 1], (idx + 1) & 1);
                load_A(scs[idx + 1], (idx + 1) & 1);
                CP_COMMIT();
                CP_WAIT(1);
            } else {
                CP_WAIT(0);
            }
            __syncthreads();

            const uint32_t base = sb + (idx & 1) * STAGE;
#pragma unroll
            for (int ks = 0; ks < 4; ks++) {
                uint32_t bfr[5][2];
#pragma unroll
                for (int e = 0; e < 5; e++)
                    ldmB(bfr[e], base + brow + e * 1152 + ks * 32);
                uint32_t afr[2][4];
#pragma unroll
                for (int f = 0; f < 2; f++)
                    ldmA(afr[f], base + arow + f * 2304 + ks * 32);
#pragma unroll
                for (int f = 0; f < 2; f++)
#pragma unroll
                    for (int e = 0; e < 5; e++)
                        mma16816(acc[f][e], afr[f], bfr[e]);
            }
            if (idx + 1 < nsc) __syncthreads();
        }
    }

    // ---- epilogue: acc -> smem pre [64 rows][160 n'] ----
    __syncthreads();
    float* pre = (float*)smem;
#pragma unroll
    for (int f = 0; f < 2; f++) {
#pragma unroll
        for (int e = 0; e < 5; e++) {
            int row = m0 + f * 16 + (lane >> 2);
            int col = n0 + e * 8 + (lane & 3) * 2;
            *(float2*)&pre[row * 160 + col]       = make_float2(acc[f][e][0], acc[f][e][1]);
            *(float2*)&pre[(row + 8) * 160 + col] = make_float2(acc[f][e][2], acc[f][e][3]);
        }
    }
    __syncthreads();

    // ---- gate math, vectorized: 512 items = 64 b x 8 h4-groups ----
    float*  __restrict__ Cc = g_C   + (size_t)cell  * (B_ * H_);
    __half* __restrict__ Sc = g_S16 + (size_t)cell  * (B_ * H_);

    float sokeep[2][4];
    int   bkeep[2], hkeep[2];

#pragma unroll
    for (int p = 0; p < 2; p++) {
        const int id = t + 256 * p;
        const int b = id >> 3;
        const int hl = (id & 7) * 4;
        const int h = htile * 32 + hl;
        bkeep[p] = b; hkeep[p] = h;

        const float* PXr = g_PX + ((size_t)i * B_ + b) * FIVEH;
        const float* PYr = g_PY + ((size_t)j * B_ + b) * FIVEH;

        float pg[5][4];
#pragma unroll
        for (int g = 0; g < 5; g++) {
            const int col = g * H_ + h;
            float4 px = *(const float4*)&PXr[col];
            float4 py = *(const float4*)&PYr[col];
            float4 bb = *(const float4*)&bias[col];
            pg[g][0] = pre[b * 160 + (hl + 0) * 5 + g] + px.x + py.x + bb.x;
            pg[g][1] = pre[b * 160 + (hl + 1) * 5 + g] + px.y + py.y + bb.y;
            pg[g][2] = pre[b * 160 + (hl + 2) * 5 + g] + px.z + py.z + bb.z;
            pg[g][3] = pre[b * 160 + (hl + 3) * 5 + g] + px.w + py.w + bb.w;
        }

        float4 ch4 = make_float4(0.f, 0.f, 0.f, 0.f);
        float4 cv4 = make_float4(0.f, 0.f, 0.f, 0.f);
        if (hh) ch4 = *(const float4*)&CH[(size_t)b * H_ + h];
        if (vv) cv4 = *(const float4*)&CV[(size_t)b * H_ + h];
        float ch[4] = {ch4.x, ch4.y, ch4.z, ch4.w};
        float cv[4] = {cv4.x, cv4.y, cv4.z, cv4.w};

        float so[4], co[4];
#pragma unroll
        for (int u = 0; u < 4; u++) {
            float ig = sigf(pg[0][u]);
            float fg = sigf(pg[1][u]);
            float og = sigf(pg[2][u]);
            float lg = sigf(pg[3][u]);
            float gg = tanhf_fast(pg[4][u]);
            float c = fg * (lg * ch[u] + (1.f - lg) * cv[u]) + ig * gg;
            co[u] = c;
            so[u] = og * tanhf_fast(c);
            sokeep[p][u] = so[u];
        }

        const size_t sidx = (size_t)b * H_ + h;
        *(float4*)&Cc[sidx] = make_float4(co[0], co[1], co[2], co[3]);
        __half sh[4];
#pragma unroll
        for (int u = 0; u < 4; u++) sh[u] = __float2half(so[u]);
        *(uint2*)&Sc[sidx] = *(uint2*)&sh[0];
    }

    // ---- publish EARLY: consumers need only C and S16 ----
    __syncthreads();
    if (t == 0) signal_cell(&g_cnt[cell]);

    // ---- output store off the critical path ----
#pragma unroll
    for (int p = 0; p < 2; p++) {
        *(float4*)&out[(((size_t)i * O_ + j) * B_ + bkeep[p]) * H_ + hkeep[p]] =
            make_float4(sokeep[p][0], sokeep[p][1], sokeep[p][2], sokeep[p][3]);
    }
}

// ---------------------------------------------------------------------------
// Persistent kernel: NO grid barriers — pure dataflow over 18432 tile tasks,
// enumerated in diagonal order, statically strided across 444 CTAs
// (deadlock-free: each CTA's list is diagonal-ordered; deps live strictly
// earlier in the order). 3 CTAs/SM.
// ---------------------------------------------------------------------------
__global__ __launch_bounds__(256, 3) void persist_kernel(
    const float* __restrict__ bias, float* __restrict__ out)
{
    extern __shared__ char smem[];
    const uint32_t sb = smem_u32(smem);

    int base = 0;
    int next = blockIdx.x;

    for (int d = 0; d < I_ + O_ - 1; d++) {
        const int i_lo = (d > O_ - 1) ? d - (O_ - 1) : 0;
        const int i_hi = (d < I_ - 1) ? d : I_ - 1;
        const int nv = i_hi - i_lo + 1;
        const int ntasks = nv * 8;

        while (next < base + ntasks) {
            const int local = next - base;
            const int q = local >> 3;
            const int htile = local & 7;
            const int i = i_lo + q;
            fused_tile(smem, sb, bias, out, i, d - i, htile);
            next += NCTA;
        }
        base += ntasks;
    }
}

// ---------------------------------------------------------------------------
extern "C" void kernel_launch(void* const* d_in, const int* in_sizes, int n_in,
                              void* d_out, int out_size)
{
    const float* x  = (const float*)d_in[0];
    const float* y  = (const float*)d_in[1];
    const float* Wx = (const float*)d_in[2];
    const float* Ws = (const float*)d_in[3];
    const float* b  = (const float*)d_in[4];
    float* out = (float*)d_out;

    cudaFuncSetAttribute(persist_kernel, cudaFuncAttributeMaxDynamicSharedMemorySize,
                         SMEM_TOTAL);

    zero_cnt_kernel<<<(CELLS + 255) / 256, 256>>>();
    split_ws_kernel<<<(FIVEH * 512 + 255) / 256, 256>>>(Ws);
    precompute_kernel<<<dim3(I_, FIVEH / 128, 2), 256>>>(x, y, Wx);
    persist_kernel<<<NCTA, 256, SMEM_TOTAL>>>(b, out);
}

// round 16
// speedup vs baseline: 1.1260x; 1.1260x over previous
#include <cuda_runtime.h>
#include <cuda_fp16.h>
#include <stdint.h>
#include <math.h>

#define B_    64
#define I_    48
#define O_    48
#define F_    256
#define H_    256
#define FIVEH 1280
#define NCTA  296               // 2 CTAs per SM

// smem per stage: B tile 160x64 fp16 (rows stride 144B) + A 64x64 fp16
#define BBYTES 23040                 // 160*144
#define APASS  9216                  // 64*144
#define STAGE  (BBYTES + APASS)      // 32256
#define NSTAGE 3
#define SMEM_TOTAL (NSTAGE*STAGE)    // 96768 (epilogue reuse: 64*160*4 = 40960)

#define CELLS (I_ * O_)              // 2304

// ---------------- scratch (device globals) ----------------------------------
__device__ float g_PX[I_ * B_ * FIVEH];          // [i][b][g*256+h]
__device__ float g_PY[O_ * B_ * FIVEH];
__device__ __half g_Wh[FIVEH * 512];             // W' fp16, [n'][k], n'=h*5+g
__device__ __half g_S16[(size_t)CELLS * B_ * H_];// s per cell (i*O+j), fp16
__device__ float  g_C[(size_t)CELLS * B_ * H_];  // c per cell, fp32
__device__ unsigned g_cnt[CELLS];                // per-cell completion counters

// ---------------- fast transcendentals (MUFU path) ---------------------------
__device__ __forceinline__ float sigf(float x) {
    return __fdividef(1.f, 1.f + __expf(-x));
}
__device__ __forceinline__ float tanhf_fast(float x) {
    float xc = fminf(fmaxf(x, -15.f), 15.f);
    float e = __expf(2.f * xc);
    return __fdividef(e - 1.f, e + 1.f);
}

__device__ __forceinline__ uint32_t smem_u32(const void* p) {
    uint32_t a;
    asm("{ .reg .u64 t; cvta.to.shared.u64 t, %1; cvt.u32.u64 %0, t; }" : "=r"(a) : "l"(p));
    return a;
}
__device__ __forceinline__ void cp16(uint32_t dst, const void* src) {
    asm volatile("cp.async.cg.shared.global [%0], [%1], 16;"
                 :: "r"(dst), "l"(src) : "memory");
}
#define CP_COMMIT() asm volatile("cp.async.commit_group;" ::: "memory")
#define CP_WAIT(n)  asm volatile("cp.async.wait_group %0;" :: "n"(n) : "memory")

__device__ __forceinline__ void ldmA(uint32_t* a, uint32_t addr) {
    asm volatile("ldmatrix.sync.aligned.m8n8.x4.shared.b16 {%0,%1,%2,%3}, [%4];"
                 : "=r"(a[0]), "=r"(a[1]), "=r"(a[2]), "=r"(a[3]) : "r"(addr));
}
__device__ __forceinline__ void ldmB(uint32_t* b, uint32_t addr) {
    asm volatile("ldmatrix.sync.aligned.m8n8.x2.shared.b16 {%0,%1}, [%2];"
                 : "=r"(b[0]), "=r"(b[1]) : "r"(addr));
}
__device__ __forceinline__ void mma16816(float* c, const uint32_t* a, const uint32_t* b) {
    asm volatile("mma.sync.aligned.m16n8k16.row.col.f32.f16.f16.f32 "
                 "{%0,%1,%2,%3}, {%4,%5,%6,%7}, {%8,%9}, {%0,%1,%2,%3};"
                 : "+f"(c[0]), "+f"(c[1]), "+f"(c[2]), "+f"(c[3])
                 : "r"(a[0]), "r"(a[1]), "r"(a[2]), "r"(a[3]), "r"(b[0]), "r"(b[1]));
}

// ---------------- dataflow flag helpers --------------------------------------
__device__ __forceinline__ void wait_cell(const unsigned* p) {
    unsigned v;
    do {
        asm volatile("ld.acquire.gpu.global.u32 %0, [%1];" : "=r"(v) : "l"(p));
    } while (v < 8u);
}
__device__ __forceinline__ void signal_cell(unsigned* p) {
    asm volatile("red.release.gpu.global.add.u32 [%0], 1;" :: "l"(p) : "memory");
}

// ---------------------------------------------------------------------------
// Setup kernels
// ---------------------------------------------------------------------------
__global__ void zero_cnt_kernel() {
    int idx = blockIdx.x * 256 + threadIdx.x;
    if (idx < CELLS) g_cnt[idx] = 0u;
}

__global__ __launch_bounds__(256) void split_ws_kernel(const float* __restrict__ Ws) {
    int idx = blockIdx.x * 256 + threadIdx.x;
    if (idx >= FIVEH * 512) return;
    int np = idx >> 9, k = idx & 511;
    int h = np / 5, g = np % 5;
    g_Wh[idx] = __float2half(Ws[k * FIVEH + g * H_ + h]);
}

__global__ __launch_bounds__(256) void precompute_kernel(
    const float* __restrict__ x, const float* __restrict__ y,
    const float* __restrict__ Wx)
{
    const int cell = blockIdx.x, n0 = blockIdx.y * 128, which = blockIdx.z;
    const float* A = which ? y : x;
    const int koff = which ? F_ : 0;
    float* P = which ? g_PY : g_PX;

    __shared__ float As[16][68];
    __shared__ float Bs[16][128];
    const int t = threadIdx.x;
    const int tx = t & 15, ty = t >> 4;
    const int lm = t >> 2, lk = (t & 3) * 4;

    float acc[4][8];
#pragma unroll
    for (int r = 0; r < 4; r++)
#pragma unroll
        for (int q = 0; q < 8; q++) acc[r][q] = 0.f;

    for (int k0 = 0; k0 < F_; k0 += 16) {
        float4 av = *(const float4*)&A[(lm * I_ + cell) * F_ + k0 + lk];
        As[lk + 0][lm] = av.x; As[lk + 1][lm] = av.y;
        As[lk + 2][lm] = av.z; As[lk + 3][lm] = av.w;
#pragma unroll
        for (int s = 0; s < 2; s++) {
            int idx = t + 256 * s;
            int kl = idx >> 5, c4 = idx & 31;
            *(float4*)&Bs[kl][c4 * 4] =
                *(const float4*)&Wx[(koff + k0 + kl) * FIVEH + n0 + c4 * 4];
        }
        __syncthreads();
#pragma unroll
        for (int k = 0; k < 16; k++) {
            float4 a4 = *(const float4*)&As[k][ty * 4];
            float4 b0 = *(const float4*)&Bs[k][tx * 8];
            float4 b1 = *(const float4*)&Bs[k][tx * 8 + 4];
            float a[4] = {a4.x, a4.y, a4.z, a4.w};
            float bb[8] = {b0.x, b0.y, b0.z, b0.w, b1.x, b1.y, b1.z, b1.w};
#pragma unroll
            for (int r = 0; r < 4; r++)
#pragma unroll
                for (int q = 0; q < 8; q++) acc[r][q] += a[r] * bb[q];
        }
        __syncthreads();
    }
#pragma unroll
    for (int r = 0; r < 4; r++) {
        int m = ty * 4 + r;
        float* dst = &P[(cell * B_ + m) * FIVEH + n0 + tx * 8];
        *(float4*)dst       = make_float4(acc[r][0], acc[r][1], acc[r][2], acc[r][3]);
        *(float4*)(dst + 4) = make_float4(acc[r][4], acc[r][5], acc[r][6], acc[r][7]);
    }
}

// ---------------------------------------------------------------------------
// Fused tile: cell (i,j) x 32-h slice. SPLIT-PHASE dependency handling:
// wait hor -> run hor k-chunks (0..3); then wait ver -> run ver chunks (4..7).
// The second-side wait overlaps with the first side's GEMM. B tile of each
// phase's first chunk is pre-issued before that phase's flag wait.
// ---------------------------------------------------------------------------
__device__ __forceinline__ void fused_tile(
    char* smem, uint32_t sb,
    const float* __restrict__ bias, float* __restrict__ out,
    int i, int j, int htile)
{
    const int t = threadIdx.x, wid = t >> 5, lane = t & 31;
    const bool hh = (i > 0), vv = (j > 0);
    const int n_base = htile * 160;
    const int cell  = i * O_ + j;
    const int cellH = cell - O_;      // (i-1, j)
    const int cellV = cell - 1;       // (i, j-1)

    const __half* __restrict__ SH = g_S16 + (size_t)cellH * (B_ * H_);
    const __half* __restrict__ SV = g_S16 + (size_t)cellV * (B_ * H_);
    const float* __restrict__ CH = g_C + (size_t)cellH * (B_ * H_);
    const float* __restrict__ CV = g_C + (size_t)cellV * (B_ * H_);

    auto load_B = [&](int sc, int buf) {
        const uint32_t base = sb + buf * STAGE;
        const int kb = sc * 64;
#pragma unroll
        for (int p = 0; p < 5; p++) {
            int idx = t + 256 * p;
            int r = idx >> 3, seg = idx & 7;
            cp16(base + r * 144 + seg * 16,
                 g_Wh + (size_t)(n_base + r) * 512 + kb + seg * 8);
        }
    };
    auto load_A = [&](int sc, int buf) {
        const uint32_t base = sb + buf * STAGE;
        const __half* S = (sc < 4) ? SH : SV;
        const int kc = (sc & 3) * 64;
#pragma unroll
        for (int p = 0; p < 2; p++) {
            int idx = t + 256 * p;
            int b = idx >> 3, seg = idx & 7;
            cp16(base + BBYTES + b * 144 + seg * 16,
                 S + (size_t)b * H_ + kc + seg * 8);
        }
    };

    // warp tiling: 2m x 4n; warp tile m32 x n40
    const int wm = wid & 1, wn = wid >> 1;
    const int m0 = wm * 32, n0 = wn * 40;
    const uint32_t arow = (uint32_t)(BBYTES + (m0 + ((lane >> 3) & 1) * 8 + (lane & 7)) * 144
                                     + (lane >> 4) * 16);
    const uint32_t brow = (uint32_t)((n0 + (lane & 7)) * 144 + ((lane >> 3) & 1) * 16);

    float acc[2][5][4];
#pragma unroll
    for (int f = 0; f < 2; f++)
#pragma unroll
        for (int e = 0; e < 5; e++)
#pragma unroll
            for (int q = 0; q < 4; q++) acc[f][e][q] = 0.f;

    // ---- one phase = 4 k-chunks (base_sc..base_sc+3), 3-buffer pipeline.
    // Contract: load_B(base_sc, bufc) was already ISSUED (not committed).
    int bufc = 0;
    auto run_phase4 = [&](int base_sc) {
        const int b0 = bufc, b1 = (bufc + 1) % NSTAGE;
        load_A(base_sc, b0);
        CP_COMMIT();                         // group: B(base) + A(base)
        load_B(base_sc + 1, b1);
        load_A(base_sc + 1, b1);
        CP_COMMIT();

        int buf = b0, buf2 = (b0 + 2) % NSTAGE;
        for (int idx = 0; idx < 4; idx++) {
            if (idx < 3) CP_WAIT(1);
            else         CP_WAIT(0);
            __syncthreads();

            if (idx + 2 < 4) {
                load_B(base_sc + idx + 2, buf2);
                load_A(base_sc + idx + 2, buf2);
                CP_COMMIT();
            }

            const uint32_t base = sb + buf * STAGE;
#pragma unroll
            for (int ks = 0; ks < 4; ks++) {
                uint32_t bfr[5][2];
#pragma unroll
                for (int e = 0; e < 5; e++)
                    ldmB(bfr[e], base + brow + e * 1152 + ks * 32);
                uint32_t afr[2][4];
#pragma unroll
                for (int f = 0; f < 2; f++)
                    ldmA(afr[f], base + arow + f * 2304 + ks * 32);
#pragma unroll
                for (int f = 0; f < 2; f++)
#pragma unroll
                    for (int e = 0; e < 5; e++)
                        mma16816(acc[f][e], afr[f], bfr[e]);
            }
            if (++buf == NSTAGE) buf = 0;
            if (++buf2 == NSTAGE) buf2 = 0;
        }
        bufc = buf;                          // next free buffer
    };

    // ---- phase sequence: first side (hor if present), then second side ----
    __syncthreads();    // protect smem reuse across tasks (epilogue of prev tile)
    if (hh) {
        load_B(0, bufc);                     // pre-issue B before the flag wait
        if (t == 0) wait_cell(&g_cnt[cellH]);
        __syncthreads();
        run_phase4(0);
    }
    if (vv) {
        load_B(4, bufc);                     // dep-free B pre-issued before wait
        if (t == 0) wait_cell(&g_cnt[cellV]);
        __syncthreads();
        run_phase4(4);
    }

    // ---- epilogue: acc -> smem pre [64 rows][160 n'] ----
    __syncthreads();
    float* pre = (float*)smem;
#pragma unroll
    for (int f = 0; f < 2; f++) {
#pragma unroll
        for (int e = 0; e < 5; e++) {
            int row = m0 + f * 16 + (lane >> 2);
            int col = n0 + e * 8 + (lane & 3) * 2;
            *(float2*)&pre[row * 160 + col]       = make_float2(acc[f][e][0], acc[f][e][1]);
            *(float2*)&pre[(row + 8) * 160 + col] = make_float2(acc[f][e][2], acc[f][e][3]);
        }
    }
    __syncthreads();

    // ---- gate math, vectorized: 512 items = 64 b x 8 h4-groups ----
    float*  __restrict__ Cc = g_C   + (size_t)cell  * (B_ * H_);
    __half* __restrict__ Sc = g_S16 + (size_t)cell  * (B_ * H_);

    float sokeep[2][4];
    int   bkeep[2], hkeep[2];

#pragma unroll
    for (int p = 0; p < 2; p++) {
        const int id = t + 256 * p;
        const int b = id >> 3;
        const int hl = (id & 7) * 4;
        const int h = htile * 32 + hl;
        bkeep[p] = b; hkeep[p] = h;

        const float* PXr = g_PX + ((size_t)i * B_ + b) * FIVEH;
        const float* PYr = g_PY + ((size_t)j * B_ + b) * FIVEH;

        float pg[5][4];
#pragma unroll
        for (int g = 0; g < 5; g++) {
            const int col = g * H_ + h;
            float4 px = *(const float4*)&PXr[col];
            float4 py = *(const float4*)&PYr[col];
            float4 bb = *(const float4*)&bias[col];
            pg[g][0] = pre[b * 160 + (hl + 0) * 5 + g] + px.x + py.x + bb.x;
            pg[g][1] = pre[b * 160 + (hl + 1) * 5 + g] + px.y + py.y + bb.y;
            pg[g][2] = pre[b * 160 + (hl + 2) * 5 + g] + px.z + py.z + bb.z;
            pg[g][3] = pre[b * 160 + (hl + 3) * 5 + g] + px.w + py.w + bb.w;
        }

        float4 ch4 = make_float4(0.f, 0.f, 0.f, 0.f);
        float4 cv4 = make_float4(0.f, 0.f, 0.f, 0.f);
        if (hh) ch4 = *(const float4*)&CH[(size_t)b * H_ + h];
        if (vv) cv4 = *(const float4*)&CV[(size_t)b * H_ + h];
        float ch[4] = {ch4.x, ch4.y, ch4.z, ch4.w};
        float cv[4] = {cv4.x, cv4.y, cv4.z, cv4.w};

        float so[4], co[4];
#pragma unroll
        for (int u = 0; u < 4; u++) {
            float ig = sigf(pg[0][u]);
            float fg = sigf(pg[1][u]);
            float og = sigf(pg[2][u]);
            float lg = sigf(pg[3][u]);
            float gg = tanhf_fast(pg[4][u]);
            float c = fg * (lg * ch[u] + (1.f - lg) * cv[u]) + ig * gg;
            co[u] = c;
            so[u] = og * tanhf_fast(c);
            sokeep[p][u] = so[u];
        }

        const size_t sidx = (size_t)b * H_ + h;
        *(float4*)&Cc[sidx] = make_float4(co[0], co[1], co[2], co[3]);
        __half sh[4];
#pragma unroll
        for (int u = 0; u < 4; u++) sh[u] = __float2half(so[u]);
        *(uint2*)&Sc[sidx] = *(uint2*)&sh[0];
    }

    // ---- publish EARLY: consumers need only C and S16 ----
    __syncthreads();
    if (t == 0) signal_cell(&g_cnt[cell]);

    // ---- output store off the critical path ----
#pragma unroll
    for (int p = 0; p < 2; p++) {
        *(float4*)&out[(((size_t)i * O_ + j) * B_ + bkeep[p]) * H_ + hkeep[p]] =
            make_float4(sokeep[p][0], sokeep[p][1], sokeep[p][2], sokeep[p][3]);
    }
}

// ---------------------------------------------------------------------------
// Persistent kernel: NO grid barriers — pure dataflow over 18432 tile tasks,
// enumerated in diagonal order, statically strided across CTAs
// (deadlock-free: each CTA's list is diagonal-ordered; deps live strictly
// earlier in the order).
// ---------------------------------------------------------------------------
__global__ __launch_bounds__(256, 2) void persist_kernel(
    const float* __restrict__ bias, float* __restrict__ out)
{
    extern __shared__ char smem[];
    const uint32_t sb = smem_u32(smem);

    int base = 0;
    int next = blockIdx.x;

    for (int d = 0; d < I_ + O_ - 1; d++) {
        const int i_lo = (d > O_ - 1) ? d - (O_ - 1) : 0;
        const int i_hi = (d < I_ - 1) ? d : I_ - 1;
        const int nv = i_hi - i_lo + 1;
        const int ntasks = nv * 8;

        while (next < base + ntasks) {
            const int local = next - base;
            const int q = local >> 3;
            const int htile = local & 7;
            const int i = i_lo + q;
            fused_tile(smem, sb, bias, out, i, d - i, htile);
            next += NCTA;
        }
        base += ntasks;
    }
}

// ---------------------------------------------------------------------------
extern "C" void kernel_launch(void* const* d_in, const int* in_sizes, int n_in,
                              void* d_out, int out_size)
{
    const float* x  = (const float*)d_in[0];
    const float* y  = (const float*)d_in[1];
    const float* Wx = (const float*)d_in[2];
    const float* Ws = (const float*)d_in[3];
    const float* b  = (const float*)d_in[4];
    float* out = (float*)d_out;

    cudaFuncSetAttribute(persist_kernel, cudaFuncAttributeMaxDynamicSharedMemorySize,
                         SMEM_TOTAL);

    zero_cnt_kernel<<<(CELLS + 255) / 256, 256>>>();
    split_ws_kernel<<<(FIVEH * 512 + 255) / 256, 256>>>(Ws);
    precompute_kernel<<<dim3(I_, FIVEH / 128, 2), 256>>>(x, y, Wx);
    persist_kernel<<<NCTA, 256, SMEM_TOTAL>>>(b, out);
}

// round 17
// speedup vs baseline: 1.1832x; 1.0508x over previous
#include <cuda_runtime.h>
#include <cuda_fp16.h>
#include <stdint.h>
#include <math.h>

#define B_    64
#define I_    48
#define O_    48
#define F_    256
#define H_    256
#define FIVEH 1280
#define NCTA  296               // 2 CTAs per SM

// smem per stage: B tile 160x64 fp16 (rows stride 144B) + A 64x64 fp16
#define BBYTES 23040                 // 160*144
#define APASS  9216                  // 64*144
#define STAGE  (BBYTES + APASS)      // 32256
#define NSTAGE 3
#define SMEM_TOTAL (NSTAGE*STAGE)    // 96768

// epilogue staging: 64 rows x 168-float stride (bank-conflict reduced),
// placed at the TAIL of smem so buffer 0 stays free for the B0 prefetch.
#define PRE_STRIDE 168
#define PRE_BYTES  (64 * PRE_STRIDE * 4)        // 43008
#define PRE_OFF    (SMEM_TOTAL - PRE_BYTES)     // 53760 (overlaps buffers 1-2 only)

#define CELLS (I_ * O_)              // 2304
#define NTASKS (CELLS * 8)           // 18432

// ---------------- scratch (device globals) ----------------------------------
__device__ float g_PX[I_ * B_ * FIVEH];          // [i][b][g*256+h]
__device__ float g_PY[O_ * B_ * FIVEH];
__device__ __half g_Wh[FIVEH * 512];             // W' fp16, [n'][k], n'=h*5+g
__device__ __half g_S16[(size_t)CELLS * B_ * H_];// s per cell (i*O+j), fp16
__device__ float  g_C[(size_t)CELLS * B_ * H_];  // c per cell, fp32
__device__ unsigned g_cnt[CELLS];                // per-cell completion counters

// ---------------- fast transcendentals (MUFU path) ---------------------------
__device__ __forceinline__ float sigf(float x) {
    return __fdividef(1.f, 1.f + __expf(-x));
}
__device__ __forceinline__ float tanhf_fast(float x) {
    float xc = fminf(fmaxf(x, -15.f), 15.f);
    float e = __expf(2.f * xc);
    return __fdividef(e - 1.f, e + 1.f);
}

__device__ __forceinline__ uint32_t smem_u32(const void* p) {
    uint32_t a;
    asm("{ .reg .u64 t; cvta.to.shared.u64 t, %1; cvt.u32.u64 %0, t; }" : "=r"(a) : "l"(p));
    return a;
}
__device__ __forceinline__ void cp16(uint32_t dst, const void* src) {
    asm volatile("cp.async.cg.shared.global [%0], [%1], 16;"
                 :: "r"(dst), "l"(src) : "memory");
}
#define CP_COMMIT() asm volatile("cp.async.commit_group;" ::: "memory")
#define CP_WAIT(n)  asm volatile("cp.async.wait_group %0;" :: "n"(n) : "memory")

__device__ __forceinline__ void ldmA(uint32_t* a, uint32_t addr) {
    asm volatile("ldmatrix.sync.aligned.m8n8.x4.shared.b16 {%0,%1,%2,%3}, [%4];"
                 : "=r"(a[0]), "=r"(a[1]), "=r"(a[2]), "=r"(a[3]) : "r"(addr));
}
__device__ __forceinline__ void ldmB(uint32_t* b, uint32_t addr) {
    asm volatile("ldmatrix.sync.aligned.m8n8.x2.shared.b16 {%0,%1}, [%2];"
                 : "=r"(b[0]), "=r"(b[1]) : "r"(addr));
}
__device__ __forceinline__ void mma16816(float* c, const uint32_t* a, const uint32_t* b) {
    asm volatile("mma.sync.aligned.m16n8k16.row.col.f32.f16.f16.f32 "
                 "{%0,%1,%2,%3}, {%4,%5,%6,%7}, {%8,%9}, {%0,%1,%2,%3};"
                 : "+f"(c[0]), "+f"(c[1]), "+f"(c[2]), "+f"(c[3])
                 : "r"(a[0]), "r"(a[1]), "r"(a[2]), "r"(a[3]), "r"(b[0]), "r"(b[1]));
}

// ---------------- dataflow flag helpers --------------------------------------
__device__ __forceinline__ void wait_cell(const unsigned* p) {
    unsigned v;
    do {
        asm volatile("ld.acquire.gpu.global.u32 %0, [%1];" : "=r"(v) : "l"(p));
    } while (v < 8u);
}
__device__ __forceinline__ void signal_cell(unsigned* p) {
    asm volatile("red.release.gpu.global.add.u32 [%0], 1;" :: "l"(p) : "memory");
}

// ---------------------------------------------------------------------------
// Setup kernels
// ---------------------------------------------------------------------------
__global__ void zero_cnt_kernel() {
    int idx = blockIdx.x * 256 + threadIdx.x;
    if (idx < CELLS) g_cnt[idx] = 0u;
}

__global__ __launch_bounds__(256) void split_ws_kernel(const float* __restrict__ Ws) {
    int idx = blockIdx.x * 256 + threadIdx.x;
    if (idx >= FIVEH * 512) return;
    int np = idx >> 9, k = idx & 511;
    int h = np / 5, g = np % 5;
    g_Wh[idx] = __float2half(Ws[k * FIVEH + g * H_ + h]);
}

__global__ __launch_bounds__(256) void precompute_kernel(
    const float* __restrict__ x, const float* __restrict__ y,
    const float* __restrict__ Wx)
{
    const int cell = blockIdx.x, n0 = blockIdx.y * 128, which = blockIdx.z;
    const float* A = which ? y : x;
    const int koff = which ? F_ : 0;
    float* P = which ? g_PY : g_PX;

    __shared__ float As[16][68];
    __shared__ float Bs[16][128];
    const int t = threadIdx.x;
    const int tx = t & 15, ty = t >> 4;
    const int lm = t >> 2, lk = (t & 3) * 4;

    float acc[4][8];
#pragma unroll
    for (int r = 0; r < 4; r++)
#pragma unroll
        for (int q = 0; q < 8; q++) acc[r][q] = 0.f;

    for (int k0 = 0; k0 < F_; k0 += 16) {
        float4 av = *(const float4*)&A[(lm * I_ + cell) * F_ + k0 + lk];
        As[lk + 0][lm] = av.x; As[lk + 1][lm] = av.y;
        As[lk + 2][lm] = av.z; As[lk + 3][lm] = av.w;
#pragma unroll
        for (int s = 0; s < 2; s++) {
            int idx = t + 256 * s;
            int kl = idx >> 5, c4 = idx & 31;
            *(float4*)&Bs[kl][c4 * 4] =
                *(const float4*)&Wx[(koff + k0 + kl) * FIVEH + n0 + c4 * 4];
        }
        __syncthreads();
#pragma unroll
        for (int k = 0; k < 16; k++) {
            float4 a4 = *(const float4*)&As[k][ty * 4];
            float4 b0 = *(const float4*)&Bs[k][tx * 8];
            float4 b1 = *(const float4*)&Bs[k][tx * 8 + 4];
            float a[4] = {a4.x, a4.y, a4.z, a4.w};
            float bb[8] = {b0.x, b0.y, b0.z, b0.w, b1.x, b1.y, b1.z, b1.w};
#pragma unroll
            for (int r = 0; r < 4; r++)
#pragma unroll
                for (int q = 0; q < 8; q++) acc[r][q] += a[r] * bb[q];
        }
        __syncthreads();
    }
#pragma unroll
    for (int r = 0; r < 4; r++) {
        int m = ty * 4 + r;
        float* dst = &P[(cell * B_ + m) * FIVEH + n0 + tx * 8];
        *(float4*)dst       = make_float4(acc[r][0], acc[r][1], acc[r][2], acc[r][3]);
        *(float4*)(dst + 4) = make_float4(acc[r][4], acc[r][5], acc[r][6], acc[r][7]);
    }
}

// ---------------------------------------------------------------------------
// Fused tile: cell (i,j) x 32-h slice. Split-phase dependency handling,
// per-tile buffer rotation reset (phase 1 always starts at buffer 0), and
// cross-tile B0 prefetch: the NEXT task's first B chunk is issued into
// buffer 0 during this tile's epilogue.
// ---------------------------------------------------------------------------
__device__ __forceinline__ void fused_tile(
    char* smem, uint32_t sb,
    const float* __restrict__ bias, float* __restrict__ out,
    int i, int j, int htile,
    bool b0_prefetched, bool pf_valid, int pf_sc, int pf_nbase)
{
    const int t = threadIdx.x, wid = t >> 5, lane = t & 31;
    const bool hh = (i > 0), vv = (j > 0);
    const int n_base = htile * 160;
    const int cell  = i * O_ + j;
    const int cellH = cell - O_;      // (i-1, j)
    const int cellV = cell - 1;       // (i, j-1)

    const __half* __restrict__ SH = g_S16 + (size_t)cellH * (B_ * H_);
    const __half* __restrict__ SV = g_S16 + (size_t)cellV * (B_ * H_);
    const float* __restrict__ CH = g_C + (size_t)cellH * (B_ * H_);
    const float* __restrict__ CV = g_C + (size_t)cellV * (B_ * H_);

    auto load_B = [&](int sc, int buf, int nb) {
        const uint32_t base = sb + buf * STAGE;
        const int kb = sc * 64;
#pragma unroll
        for (int p = 0; p < 5; p++) {
            int idx = t + 256 * p;
            int r = idx >> 3, seg = idx & 7;
            cp16(base + r * 144 + seg * 16,
                 g_Wh + (size_t)(nb + r) * 512 + kb + seg * 8);
        }
    };
    auto load_A = [&](int sc, int buf) {
        const uint32_t base = sb + buf * STAGE;
        const __half* S = (sc < 4) ? SH : SV;
        const int kc = (sc & 3) * 64;
#pragma unroll
        for (int p = 0; p < 2; p++) {
            int idx = t + 256 * p;
            int b = idx >> 3, seg = idx & 7;
            cp16(base + BBYTES + b * 144 + seg * 16,
                 S + (size_t)b * H_ + kc + seg * 8);
        }
    };

    // warp tiling: 2m x 4n; warp tile m32 x n40
    const int wm = wid & 1, wn = wid >> 1;
    const int m0 = wm * 32, n0 = wn * 40;
    const uint32_t arow = (uint32_t)(BBYTES + (m0 + ((lane >> 3) & 1) * 8 + (lane & 7)) * 144
                                     + (lane >> 4) * 16);
    const uint32_t brow = (uint32_t)((n0 + (lane & 7)) * 144 + ((lane >> 3) & 1) * 16);

    float acc[2][5][4];
#pragma unroll
    for (int f = 0; f < 2; f++)
#pragma unroll
        for (int e = 0; e < 5; e++)
#pragma unroll
            for (int q = 0; q < 4; q++) acc[f][e][q] = 0.f;

    // ---- one phase = 4 k-chunks, 3-buffer pipeline.
    // Contract: load_B(base_sc, bufc) was already ISSUED (not committed).
    int bufc = 0;
    auto run_phase4 = [&](int base_sc) {
        const int b0 = bufc, b1 = (bufc + 1) % NSTAGE;
        load_A(base_sc, b0);
        CP_COMMIT();                         // group: B(base) + A(base)
        load_B(base_sc + 1, b1, n_base);
        load_A(base_sc + 1, b1);
        CP_COMMIT();

        int buf = b0, buf2 = (b0 + 2) % NSTAGE;
        for (int idx = 0; idx < 4; idx++) {
            if (idx < 3) CP_WAIT(1);
            else         CP_WAIT(0);
            __syncthreads();

            if (idx + 2 < 4) {
                load_B(base_sc + idx + 2, buf2, n_base);
                load_A(base_sc + idx + 2, buf2);
                CP_COMMIT();
            }

            const uint32_t base = sb + buf * STAGE;
#pragma unroll
            for (int ks = 0; ks < 4; ks++) {
                uint32_t bfr[5][2];
#pragma unroll
                for (int e = 0; e < 5; e++)
                    ldmB(bfr[e], base + brow + e * 1152 + ks * 32);
                uint32_t afr[2][4];
#pragma unroll
                for (int f = 0; f < 2; f++)
                    ldmA(afr[f], base + arow + f * 2304 + ks * 32);
#pragma unroll
                for (int f = 0; f < 2; f++)
#pragma unroll
                    for (int e = 0; e < 5; e++)
                        mma16816(acc[f][e], afr[f], bfr[e]);
            }
            if (++buf == NSTAGE) buf = 0;
            if (++buf2 == NSTAGE) buf2 = 0;
        }
        bufc = buf;                          // next free buffer
    };

    // ---- phase sequence ----
    __syncthreads();    // smem reuse safety (prev tile's epilogue reads done)
    const int first_sc = hh ? 0 : 4;
    const bool any = hh || vv;
    if (any && !b0_prefetched) load_B(first_sc, 0, n_base);   // issued, uncommitted

    if (hh) {
        if (t == 0) wait_cell(&g_cnt[cellH]);
        __syncthreads();
        run_phase4(0);
    }
    if (vv) {
        if (hh) load_B(4, bufc, n_base);     // ver B pre-issued before ver wait
        if (t == 0) wait_cell(&g_cnt[cellV]);
        __syncthreads();
        run_phase4(4);
    }

    // ---- epilogue: acc -> smem pre [64 rows][PRE_STRIDE] at tail ----
    __syncthreads();                          // all MMA done (buffer 0 now safe)
    if (pf_valid) load_B(pf_sc, 0, pf_nbase); // NEXT task's B0, hidden by epilogue

    float* pre = (float*)(smem + PRE_OFF);
#pragma unroll
    for (int f = 0; f < 2; f++) {
#pragma unroll
        for (int e = 0; e < 5; e++) {
            int row = m0 + f * 16 + (lane >> 2);
            int col = n0 + e * 8 + (lane & 3) * 2;
            *(float2*)&pre[row * PRE_STRIDE + col]       = make_float2(acc[f][e][0], acc[f][e][1]);
            *(float2*)&pre[(row + 8) * PRE_STRIDE + col] = make_float2(acc[f][e][2], acc[f][e][3]);
        }
    }
    __syncthreads();

    // ---- gate math, vectorized: 512 items = 64 b x 8 h4-groups ----
    float*  __restrict__ Cc = g_C   + (size_t)cell  * (B_ * H_);
    __half* __restrict__ Sc = g_S16 + (size_t)cell  * (B_ * H_);

    float sokeep[2][4];
    int   bkeep[2], hkeep[2];

#pragma unroll
    for (int p = 0; p < 2; p++) {
        const int id = t + 256 * p;
        const int b = id >> 3;
        const int hl = (id & 7) * 4;
        const int h = htile * 32 + hl;
        bkeep[p] = b; hkeep[p] = h;

        const float* PXr = g_PX + ((size_t)i * B_ + b) * FIVEH;
        const float* PYr = g_PY + ((size_t)j * B_ + b) * FIVEH;

        float pg[5][4];
#pragma unroll
        for (int g = 0; g < 5; g++) {
            const int col = g * H_ + h;
            float4 px = *(const float4*)&PXr[col];
            float4 py = *(const float4*)&PYr[col];
            float4 bb = *(const float4*)&bias[col];
            pg[g][0] = pre[b * PRE_STRIDE + (hl + 0) * 5 + g] + px.x + py.x + bb.x;
            pg[g][1] = pre[b * PRE_STRIDE + (hl + 1) * 5 + g] + px.y + py.y + bb.y;
            pg[g][2] = pre[b * PRE_STRIDE + (hl + 2) * 5 + g] + px.z + py.z + bb.z;
            pg[g][3] = pre[b * PRE_STRIDE + (hl + 3) * 5 + g] + px.w + py.w + bb.w;
        }

        float4 ch4 = make_float4(0.f, 0.f, 0.f, 0.f);
        float4 cv4 = make_float4(0.f, 0.f, 0.f, 0.f);
        if (hh) ch4 = *(const float4*)&CH[(size_t)b * H_ + h];
        if (vv) cv4 = *(const float4*)&CV[(size_t)b * H_ + h];
        float ch[4] = {ch4.x, ch4.y, ch4.z, ch4.w};
        float cv[4] = {cv4.x, cv4.y, cv4.z, cv4.w};

        float so[4], co[4];
#pragma unroll
        for (int u = 0; u < 4; u++) {
            float ig = sigf(pg[0][u]);
            float fg = sigf(pg[1][u]);
            float og = sigf(pg[2][u]);
            float lg = sigf(pg[3][u]);
            float gg = tanhf_fast(pg[4][u]);
            float c = fg * (lg * ch[u] + (1.f - lg) * cv[u]) + ig * gg;
            co[u] = c;
            so[u] = og * tanhf_fast(c);
            sokeep[p][u] = so[u];
        }

        const size_t sidx = (size_t)b * H_ + h;
        *(float4*)&Cc[sidx] = make_float4(co[0], co[1], co[2], co[3]);
        __half sh[4];
#pragma unroll
        for (int u = 0; u < 4; u++) sh[u] = __float2half(so[u]);
        *(uint2*)&Sc[sidx] = *(uint2*)&sh[0];
    }

    // ---- publish EARLY: consumers need only C and S16 ----
    __syncthreads();
    if (t == 0) signal_cell(&g_cnt[cell]);

    // ---- output store off the critical path ----
#pragma unroll
    for (int p = 0; p < 2; p++) {
        *(float4*)&out[(((size_t)i * O_ + j) * B_ + bkeep[p]) * H_ + hkeep[p]] =
            make_float4(sokeep[p][0], sokeep[p][1], sokeep[p][2], sokeep[p][3]);
    }
}

// ---------------------------------------------------------------------------
// Persistent kernel: pure dataflow over 18432 tile tasks in diagonal order,
// statically strided across CTAs; next-task B0 prefetch threaded through.
// ---------------------------------------------------------------------------
__global__ __launch_bounds__(256, 2) void persist_kernel(
    const float* __restrict__ bias, float* __restrict__ out)
{
    extern __shared__ char smem[];
    const uint32_t sb = smem_u32(smem);

    int d = 0, base = 0, nv = 1;
    bool b0_pf = false;

    for (int tk = blockIdx.x; tk < NTASKS; tk += NCTA) {
        while (tk >= base + nv * 8) {
            base += nv * 8;
            d++;
            nv = (d < I_) ? d + 1 : (I_ + O_ - 1) - d;
        }
        const int local = tk - base;
        const int i_lo = (d > O_ - 1) ? d - (O_ - 1) : 0;
        const int i = i_lo + (local >> 3);
        const int j = d - i;
        const int ht = local & 7;

        // decode next task for the B0 prefetch
        const int tk2 = tk + NCTA;
        bool pf_valid = (tk2 < NTASKS);
        int pf_sc = 0, pf_nb = 0;
        if (pf_valid) {
            int d2 = d, base2 = base, nv2 = nv;
            while (tk2 >= base2 + nv2 * 8) {
                base2 += nv2 * 8;
                d2++;
                nv2 = (d2 < I_) ? d2 + 1 : (I_ + O_ - 1) - d2;
            }
            const int l2 = tk2 - base2;
            const int ilo2 = (d2 > O_ - 1) ? d2 - (O_ - 1) : 0;
            const int i2 = ilo2 + (l2 >> 3);
            const int j2 = d2 - i2;
            if (i2 == 0 && j2 == 0) pf_valid = false;   // corner has no GEMM
            pf_sc = (i2 > 0) ? 0 : 4;
            pf_nb = (l2 & 7) * 160;
        }

        fused_tile(smem, sb, bias, out, i, j, ht, b0_pf, pf_valid, pf_sc, pf_nb);
        b0_pf = pf_valid;
    }
}

// ---------------------------------------------------------------------------
extern "C" void kernel_launch(void* const* d_in, const int* in_sizes, int n_in,
                              void* d_out, int out_size)
{
    const float* x  = (const float*)d_in[0];
    const float* y  = (const float*)d_in[1];
    const float* Wx = (const float*)d_in[2];
    const float* Ws = (const float*)d_in[3];
    const float* b  = (const float*)d_in[4];
    float* out = (float*)d_out;

    cudaFuncSetAttribute(persist_kernel, cudaFuncAttributeMaxDynamicSharedMemorySize,
                         SMEM_TOTAL);

    zero_cnt_kernel<<<(CELLS + 255) / 256, 256>>>();
    split_ws_kernel<<<(FIVEH * 512 + 255) / 256, 256>>>(Ws);
    precompute_kernel<<<dim3(I_, FIVEH / 128, 2), 256>>>(x, y, Wx);
    persist_kernel<<<NCTA, 256, SMEM_TOTAL>>>(b, out);
}